// round 16
// baseline (speedup 1.0000x reference)
#include <cuda_runtime.h>
#include <cuda_fp16.h>
#include <mma.h>

using namespace nvcuda;

#define NN 100000
#define EE 3200000
#define HH 64
#define BCAP 128   // bucket capacity per node (deg ~ Poisson(32); P(>128) ~ 1e-40)

// ---------------- scratch (static device globals; no allocation) ----------------
__device__ int   g_cnt[NN];
__device__ int   g_colB[(size_t)NN * BCAP];
__device__ __align__(16) __half g_hs[NN * HH];   // features for gather (fp16)
__device__ __align__(16) float  g_x[NN * HH];    // layer activations (fp32)
__device__ int   g_is64;

// packed f32x2 helpers
#define PK2(dst, lo, hi)  asm("mov.b64 %0, {%1, %2};" : "=l"(dst) : "f"(lo), "f"(hi))
#define UPK2(lo, hi, src) asm("mov.b64 {%0, %1}, %2;" : "=f"(lo), "=f"(hi) : "l"(src))
#define FMA2(acc, a, b)   asm("fma.rn.f32x2 %0, %1, %2, %0;" : "+l"(acc) : "l"(a), "l"(b))
#define ADD2(acc, a)      asm("add.rn.f32x2 %0, %0, %1;" : "+l"(acc) : "l"(a))

// convert half2 (as unsigned) -> packed f32x2 (as u64)
__device__ __forceinline__ unsigned long long h2_to_f32x2(unsigned h) {
    float2 f = __half22float2(*(__half2*)&h);
    unsigned long long r;
    PK2(r, f.x, f.y);
    return r;
}

// ---------------- prep: zero counts + parallel edge-dtype detect ----------------
__global__ void k_prep(const int* __restrict__ ei32) {
    int i = blockIdx.x * blockDim.x + threadIdx.x;
    if (i < NN) g_cnt[i] = 0;
    if (blockIdx.x == 0) {
        __shared__ int cnt;
        if (threadIdx.x == 0) cnt = 0;
        __syncthreads();
        int z = 0;
#pragma unroll
        for (int r = 0; r < 8; r++) {
            int k = 1 + 2 * (threadIdx.x * 8 + r);
            z += (ei32[k] == 0);
        }
#pragma unroll
        for (int o = 16; o; o >>= 1) z += __shfl_xor_sync(0xffffffffu, z, o);
        if ((threadIdx.x & 31) == 0) atomicAdd(&cnt, z);
        __syncthreads();
        if (threadIdx.x == 0) g_is64 = (cnt >= 1536) ? 1 : 0;
    }
}

__device__ __forceinline__ int2 edge_pair(const void* ei, size_t idx2) {
    if (g_is64) {
        longlong2 v = ((const longlong2*)ei)[idx2];
        return make_int2((int)v.x, (int)v.y);
    }
    return ((const int2*)ei)[idx2];
}

// ---------------- single-pass bucketed adjacency build ----------------
__global__ void k_fillB(const void* __restrict__ ei) {
    int e2 = blockIdx.x * blockDim.x + threadIdx.x;
    if (e2 < EE / 2) {
        int2 s = edge_pair(ei, (size_t)e2);
        int2 d = edge_pair(ei, (size_t)(EE / 2) + e2);
        int p0 = atomicAdd(&g_cnt[d.x], 1);
        if (p0 < BCAP) g_colB[(size_t)d.x * BCAP + p0] = s.x;
        int p1 = atomicAdd(&g_cnt[d.y], 1);
        if (p1 < BCAP) g_colB[(size_t)d.y * BCAP + p1] = s.y;
    }
}

// pack float4 -> 4 halves (uint2)
__device__ __forceinline__ uint2 pack_h4(float a, float b, float c, float d) {
    __half2 lo = __floats2half2_rn(a, b);
    __half2 hi = __floats2half2_rn(c, d);
    uint2 r;
    r.x = *(unsigned*)&lo;
    r.y = *(unsigned*)&hi;
    return r;
}

// ---------------- fused encoders + GCN0 linear (UNSCALED) : u0 = fp16(relu-concat @ W0) ----------------
#define XS_STRIDE 200   // halves per row (192 + 8 pad)
__global__ void __launch_bounds__(512, 3) k_enc0(
    const float* __restrict__ xf, const float* __restrict__ xw, const float* __restrict__ xt,
    const float* __restrict__ wf, const float* __restrict__ bfir,
    const float* __restrict__ ww, const float* __restrict__ bwea,
    const float* __restrict__ wt, const float* __restrict__ bter,
    const float* __restrict__ W0)
{
    extern __shared__ __align__(16) float sm[];
    float*  Csh   = sm;                     // 64*68 f (stage B)
    float*  Wcomb = sm;                     // 12*192 = 2304 f
    float*  Benc  = Wcomb + 2304;           // 192 f
    float*  raw   = Benc + 192;             // 64*33 = 2112 f
    __half* Wsh   = (__half*)(sm + 4608);   // 12288 h
    __half* xsh   = Wsh + 12288;            // 64*200 h
    const int t = threadIdx.x;

    for (int i = t; i < 12288; i += 512) Wsh[i] = __float2half(W0[i]);
    for (int i = t; i < 2304; i += 512) {
        int k = i / 192, c = i - k * 192;
        float v = 0.f;
        if (c < 64)       { if (k < 8)  v = wf[k * 64 + c]; }
        else if (c < 128) { if (k < 12) v = ww[k * 64 + (c - 64)]; }
        else              { if (k < 10) v = wt[k * 64 + (c - 128)]; }
        Wcomb[i] = v;
    }
    if (t < 64) { Benc[t] = bfir[t]; Benc[64 + t] = bwea[t]; Benc[128 + t] = bter[t]; }

    const int n0g = blockIdx.x * 64;
    for (int i = t; i < 512; i += 512) { int n = i >> 3, k = i & 7;  int gn = n0g + n; raw[n * 33 + k]      = (gn < NN) ? xf[gn * 8 + k]  : 0.f; }
    for (int i = t; i < 768; i += 512) { int n = i / 12, k = i % 12; int gn = n0g + n; raw[n * 33 + 8 + k]  = (gn < NN) ? xw[gn * 12 + k] : 0.f; }
    for (int i = t; i < 640; i += 512) { int n = i / 10, k = i % 10; int gn = n0g + n; raw[n * 33 + 20 + k] = (gn < NN) ? xt[gn * 10 + k] : 0.f; }
    if (t < 64) { raw[t * 33 + 30] = 0.f; raw[t * 33 + 31] = 0.f; }
    __syncthreads();

    // stage A: warp-uniform columns; progressive stores
    {
        const int n = t & 63, g = t >> 6;
        const float* rawn = raw + n * 33;
        uint4* dst = (uint4*)&xsh[n * XS_STRIDE + g * 24];
#pragma unroll
        for (int jg = 0; jg < 3; jg++) {
            unsigned obuf[4];
#pragma unroll
            for (int jp = 0; jp < 4; jp++) {
                float v2[2];
#pragma unroll
                for (int h = 0; h < 2; h++) {
                    const int c = g * 24 + jg * 8 + jp * 2 + h;
                    const int koff = (c < 64) ? 0 : ((c < 128) ? 8 : 20);
                    float v = Benc[c];
#pragma unroll
                    for (int k = 0; k < 12; k++)
                        v = fmaf(rawn[koff + k], Wcomb[k * 192 + c], v);
                    v2[h] = fmaxf(v, 0.f);
                }
                __half2 hh = __floats2half2_rn(v2[0], v2[1]);
                obuf[jp] = *(unsigned*)&hh;
            }
            dst[jg] = make_uint4(obuf[0], obuf[1], obuf[2], obuf[3]);
        }
    }
    __syncthreads();

    // stage B: tensor cores
    {
        const int wid = t >> 5;
        const int wm = wid >> 2, wn = wid & 3;
        wmma::fragment<wmma::matrix_a, 16, 16, 16, __half, wmma::row_major> a;
        wmma::fragment<wmma::matrix_b, 16, 16, 16, __half, wmma::row_major> b;
        wmma::fragment<wmma::accumulator, 16, 16, 16, float> c;
        wmma::fill_fragment(c, 0.0f);
#pragma unroll
        for (int kt = 0; kt < 12; kt++) {
            wmma::load_matrix_sync(a, xsh + wm * 16 * XS_STRIDE + kt * 16, XS_STRIDE);
            wmma::load_matrix_sync(b, Wsh + kt * 16 * 64 + wn * 16, 64);
            wmma::mma_sync(c, a, b, c);
        }
        wmma::store_matrix_sync(Csh + wm * 16 * 68 + wn * 16, c, 68, wmma::mem_row_major);
    }
    __syncthreads();

    // epilogue: pack fp16 UNSCALED (dinv applied inside gather0)
    {
        const int n = t >> 3, cb = (t & 7) * 8;
        const int gn = n0g + n;
        if (gn < NN) {
            const float* cr = Csh + n * 68 + cb;
            uint2 lo = pack_h4(cr[0], cr[1], cr[2], cr[3]);
            uint2 hi = pack_h4(cr[4], cr[5], cr[6], cr[7]);
            uint4 o = make_uint4(lo.x, lo.y, hi.x, hi.y);
            *(uint4*)&g_hs[(size_t)gn * 64 + cb] = o;
        }
    }
}

// ---------------- GCN linear : hs = fp16(dinv .* (x @ W)) , packed f32x2 FMA ----------------
__global__ void __launch_bounds__(256) k_lin(const float* __restrict__ W)
{
    __shared__ __align__(16) float Ws[4096];
    __shared__ __align__(16) float xs[128 * 68];
    const int t = threadIdx.x;
    for (int i = t; i < 4096; i += 256) Ws[i] = W[i];

    const int n0g = blockIdx.x * 128;
    for (int i = t; i < 2048; i += 256) {
        int n = i >> 4, k4 = i & 15;
        int gn = n0g + n;
        float4 v = (gn < NN) ? *(const float4*)&g_x[(size_t)gn * 64 + k4 * 4] : make_float4(0, 0, 0, 0);
        *(float4*)&xs[n * 68 + k4 * 4] = v;
    }
    __syncthreads();

    const int cg = t & 15, rg = t >> 4;
    const int n0 = rg * 8, c0 = cg * 4;
    unsigned long long acc01[8], acc23[8];
#pragma unroll
    for (int i = 0; i < 8; i++) { acc01[i] = 0; acc23[i] = 0; }

#pragma unroll 4
    for (int k = 0; k < 64; k++) {
        float4 b = *(const float4*)&Ws[k * 64 + c0];
        unsigned long long b01, b23;
        PK2(b01, b.x, b.y);
        PK2(b23, b.z, b.w);
#pragma unroll
        for (int i = 0; i < 8; i++) {
            float a = xs[(n0 + i) * 68 + k];
            unsigned long long aa;
            PK2(aa, a, a);
            FMA2(acc01[i], aa, b01);
            FMA2(acc23[i], aa, b23);
        }
    }
#pragma unroll
    for (int i = 0; i < 8; i++) {
        int gn = n0g + n0 + i;
        if (gn < NN) {
            float di = rsqrtf((float)g_cnt[gn] + 1.0f);
            float a0, a1, a2, a3;
            UPK2(a0, a1, acc01[i]);
            UPK2(a2, a3, acc23[i]);
            uint2 o = pack_h4(di * a0, di * a1, di * a2, di * a3);
            *(uint2*)&g_hs[(size_t)gn * 64 + c0] = o;
        }
    }
}

// ---------------- gather aggregation (templated) ----------------
// APPLY=1 (layer 0): hs UNSCALED; acc = di*u_i + sum dv_j*u_j  (packed FMA2)
// APPLY=0 (layers 1,2): hs pre-scaled; acc = hs_i + sum hs_j   (packed ADD2)
// x = relu(di * acc + b). 4 nodes/warp, 4-edge batches, reg-capped for 5 CTAs/SM.
template<int APPLY>
__global__ void __launch_bounds__(256, 5) k_gather(const float* __restrict__ bias)
{
    const int lane = threadIdx.x & 31;
    const int warp = threadIdx.x >> 5;
    const int q  = lane >> 3;
    const int ql = lane & 7;
    const int node = blockIdx.x * 32 + warp * 4 + q;

    const int deg = g_cnt[node];
    const int* colb = g_colB + (size_t)node * BCAP;
    const float di = rsqrtf((float)deg + 1.0f);

    uint4 self = *(const uint4*)&g_hs[(size_t)node * 64 + ql * 8];
    unsigned long long acc0 = h2_to_f32x2(self.x);
    unsigned long long acc1 = h2_to_f32x2(self.y);
    unsigned long long acc2 = h2_to_f32x2(self.z);
    unsigned long long acc3 = h2_to_f32x2(self.w);
    if (APPLY) {   // scale self term by di
        unsigned long long dd;
        PK2(dd, di, di);
        unsigned long long z0 = 0, z1 = 0, z2 = 0, z3 = 0;
        FMA2(z0, dd, acc0); FMA2(z1, dd, acc1); FMA2(z2, dd, acc2); FMA2(z3, dd, acc3);
        acc0 = z0; acc1 = z1; acc2 = z2; acc3 = z3;
    }

    int p = 0;
    while (true) {
        int rem = deg - p;
        int mx = rem;
        mx = max(mx, __shfl_xor_sync(0xffffffffu, mx, 8));
        mx = max(mx, __shfl_xor_sync(0xffffffffu, mx, 16));
        if (mx <= 0) break;
        int cnt = min(4, max(rem, 0));
        int idx = (ql < 4 && ql < cnt) ? colb[p + ql] : 0;
        float dvl = 1.0f;
        if (APPLY) dvl = rsqrtf((float)g_cnt[idx] + 1.0f);

        uint4 v[4];
        float dv[4];
#pragma unroll
        for (int r = 0; r < 4; r++) {
            int j = __shfl_sync(0xffffffffu, idx, (q << 3) + r);
            if (APPLY) dv[r] = __shfl_sync(0xffffffffu, dvl, (q << 3) + r);
            v[r] = (r < cnt) ? *(const uint4*)&g_hs[(size_t)j * 64 + ql * 8]
                             : make_uint4(0u, 0u, 0u, 0u);
        }
#pragma unroll
        for (int r = 0; r < 4; r++) {
            unsigned long long f0 = h2_to_f32x2(v[r].x);
            unsigned long long f1 = h2_to_f32x2(v[r].y);
            unsigned long long f2 = h2_to_f32x2(v[r].z);
            unsigned long long f3 = h2_to_f32x2(v[r].w);
            if (APPLY) {
                unsigned long long dd;
                PK2(dd, dv[r], dv[r]);
                FMA2(acc0, dd, f0);
                FMA2(acc1, dd, f1);
                FMA2(acc2, dd, f2);
                FMA2(acc3, dd, f3);
            } else {
                ADD2(acc0, f0);
                ADD2(acc1, f1);
                ADD2(acc2, f2);
                ADD2(acc3, f3);
            }
        }
        p += 4;
    }

    float a0x, a0y, a1x, a1y, a2x, a2y, a3x, a3y;
    UPK2(a0x, a0y, acc0);
    UPK2(a1x, a1y, acc1);
    UPK2(a2x, a2y, acc2);
    UPK2(a3x, a3y, acc3);
    float4 bA = *(const float4*)&bias[ql * 8];
    float4 bB = *(const float4*)&bias[ql * 8 + 4];
    float4 oA, oB;
    oA.x = fmaxf(fmaf(di, a0x, bA.x), 0.f);
    oA.y = fmaxf(fmaf(di, a0y, bA.y), 0.f);
    oA.z = fmaxf(fmaf(di, a1x, bA.z), 0.f);
    oA.w = fmaxf(fmaf(di, a1y, bA.w), 0.f);
    oB.x = fmaxf(fmaf(di, a2x, bB.x), 0.f);
    oB.y = fmaxf(fmaf(di, a2y, bB.y), 0.f);
    oB.z = fmaxf(fmaf(di, a3x, bB.z), 0.f);
    oB.w = fmaxf(fmaf(di, a3y, bB.w), 0.f);
    *(float4*)&g_x[(size_t)node * 64 + ql * 8]     = oA;
    *(float4*)&g_x[(size_t)node * 64 + ql * 8 + 4] = oB;
}

// ---------------- output MLP : out = relu(x @ W1 + b1) @ W2 + b2 (128 nodes/block) ----------------
__global__ void __launch_bounds__(256) k_out(
    const float* __restrict__ W1, const float* __restrict__ B1,
    const float* __restrict__ W2, const float* __restrict__ B2,
    float* __restrict__ out)
{
    __shared__ float W1s[2048];
    __shared__ float W2s[32];
    __shared__ float B1s[32];
    __shared__ float xsh[8][64];
    const int t = threadIdx.x;
    for (int i = t; i < 2048; i += 256) W1s[i] = W1[i];
    if (t < 32) { W2s[t] = W2[t]; B1s[t] = B1[t]; }
    __syncthreads();

    const int lane = t & 31, w = t >> 5;
#pragma unroll 1
    for (int it = 0; it < 16; it++) {
        const int node = blockIdx.x * 128 + it * 8 + w;
        if (node < NN) {
            xsh[w][lane]      = g_x[(size_t)node * 64 + lane];
            xsh[w][32 + lane] = g_x[(size_t)node * 64 + 32 + lane];
            __syncwarp();
            float m = B1s[lane];
#pragma unroll
            for (int k = 0; k < 64; k++) m = fmaf(xsh[w][k], W1s[k * 32 + lane], m);
            m = fmaxf(m, 0.f) * W2s[lane];
#pragma unroll
            for (int off = 16; off; off >>= 1) m += __shfl_xor_sync(0xffffffffu, m, off);
            if (lane == 0) out[node] = m + B2[0];
            __syncwarp();
        }
    }
}

// ---------------- launch ----------------
extern "C" void kernel_launch(void* const* d_in, const int* in_sizes, int n_in,
                              void* d_out, int out_size)
{
    const float* xf  = (const float*)d_in[0];
    const float* xw  = (const float*)d_in[1];
    const float* xt  = (const float*)d_in[2];
    const void*  ei  = d_in[3];
    const float* wf  = (const float*)d_in[4];
    const float* bf  = (const float*)d_in[5];
    const float* ww  = (const float*)d_in[6];
    const float* bw  = (const float*)d_in[7];
    const float* wt  = (const float*)d_in[8];
    const float* bt  = (const float*)d_in[9];
    const float* w0  = (const float*)d_in[10];
    const float* b0  = (const float*)d_in[11];
    const float* w1  = (const float*)d_in[12];
    const float* b1  = (const float*)d_in[13];
    const float* w2  = (const float*)d_in[14];
    const float* b2  = (const float*)d_in[15];
    const float* ow1 = (const float*)d_in[16];
    const float* ob1 = (const float*)d_in[17];
    const float* ow2 = (const float*)d_in[18];
    const float* ob2 = (const float*)d_in[19];
    float* out = (float*)d_out;

    // one-time host-side objects (no device memory involved)
    static cudaStream_t sB = nullptr;
    static cudaEvent_t  eFork = nullptr, eEnc = nullptr;
    if (sB == nullptr) {
        cudaStreamCreateWithFlags(&sB, cudaStreamNonBlocking);
        cudaEventCreateWithFlags(&eFork, cudaEventDisableTiming);
        cudaEventCreateWithFlags(&eEnc,  cudaEventDisableTiming);
    }

    const int ENC_SMEM = 4608 * 4 + 12288 * 2 + 64 * XS_STRIDE * 2;  // 68608 B
    cudaFuncSetAttribute(k_enc0, cudaFuncAttributeMaxDynamicSharedMemorySize, ENC_SMEM);

    const int encTiles = (NN + 63) / 64;     // 1563
    const int linTiles = (NN + 127) / 128;   // 782
    const int gBlocks  = NN / 32;            // 3125
    const int oBlocks  = (NN + 127) / 128;   // 782
    const int ePairs   = EE / 2;

    // fork: enc0 (unscaled, edge-independent) on sB; adjacency build on main stream
    cudaEventRecord(eFork, 0);
    cudaStreamWaitEvent(sB, eFork, 0);
    k_enc0<<<encTiles, 512, ENC_SMEM, sB>>>(xf, xw, xt, wf, bf, ww, bw, wt, bt, w0);  // launch 1
    cudaEventRecord(eEnc, sB);

    k_prep<<<(NN + 255) / 256, 256>>>((const int*)ei);          // launch 2
    k_fillB<<<(ePairs + 255) / 256, 256>>>(ei);                 // launch 3

    // join, then layer 0 gather (launch 4 -> ncu capture target)
    cudaStreamWaitEvent(0, eEnc, 0);
    k_gather<1><<<gBlocks, 256>>>(b0);
    // layer 1
    k_lin<<<linTiles, 256>>>(w1);
    k_gather<0><<<gBlocks, 256>>>(b1);
    // layer 2
    k_lin<<<linTiles, 256>>>(w2);
    k_gather<0><<<gBlocks, 256>>>(b2);
    // output MLP
    k_out<<<oBlocks, 256>>>(ow1, ob1, ow2, ob2, out);
}

// round 17
// speedup vs baseline: 1.5438x; 1.5438x over previous
#include <cuda_runtime.h>
#include <cuda_fp16.h>
#include <mma.h>

using namespace nvcuda;

#define NN 100000
#define EE 3200000
#define HH 64
#define BCAP 128   // bucket capacity per node (deg ~ Poisson(32); P(>128) ~ 1e-40)

// ---------------- scratch (static device globals; no allocation) ----------------
__device__ int   g_cnt[NN];
__device__ int   g_colB[(size_t)NN * BCAP];
__device__ __align__(16) __half g_hs[NN * HH];   // scaled features for gather (fp16)
__device__ __align__(16) float  g_x[NN * HH];    // layer activations (fp32)
__device__ int   g_is64;

// packed f32x2 helpers (used in k_lin where packs are reused)
#define PK2(dst, lo, hi)  asm("mov.b64 %0, {%1, %2};" : "=l"(dst) : "f"(lo), "f"(hi))
#define UPK2(lo, hi, src) asm("mov.b64 {%0, %1}, %2;" : "=f"(lo), "=f"(hi) : "l"(src))
#define FMA2(acc, a, b)   asm("fma.rn.f32x2 %0, %1, %2, %0;" : "+l"(acc) : "l"(a), "l"(b))

// ---------------- prep: zero counts + parallel edge-dtype detect ----------------
__global__ void k_prep(const int* __restrict__ ei32) {
    int i = blockIdx.x * blockDim.x + threadIdx.x;
    if (i < NN) g_cnt[i] = 0;
    if (blockIdx.x == 0) {
        __shared__ int cnt;
        if (threadIdx.x == 0) cnt = 0;
        __syncthreads();
        int z = 0;
#pragma unroll
        for (int r = 0; r < 8; r++) {
            int k = 1 + 2 * (threadIdx.x * 8 + r);
            z += (ei32[k] == 0);
        }
#pragma unroll
        for (int o = 16; o; o >>= 1) z += __shfl_xor_sync(0xffffffffu, z, o);
        if ((threadIdx.x & 31) == 0) atomicAdd(&cnt, z);
        __syncthreads();
        if (threadIdx.x == 0) g_is64 = (cnt >= 1536) ? 1 : 0;
    }
}

__device__ __forceinline__ int2 edge_pair(const void* ei, size_t idx2) {
    if (g_is64) {
        longlong2 v = ((const longlong2*)ei)[idx2];
        return make_int2((int)v.x, (int)v.y);
    }
    return ((const int2*)ei)[idx2];
}

// ---------------- single-pass bucketed adjacency build ----------------
__global__ void k_fillB(const void* __restrict__ ei) {
    int e2 = blockIdx.x * blockDim.x + threadIdx.x;
    if (e2 < EE / 2) {
        int2 s = edge_pair(ei, (size_t)e2);
        int2 d = edge_pair(ei, (size_t)(EE / 2) + e2);
        int p0 = atomicAdd(&g_cnt[d.x], 1);
        if (p0 < BCAP) g_colB[(size_t)d.x * BCAP + p0] = s.x;
        int p1 = atomicAdd(&g_cnt[d.y], 1);
        if (p1 < BCAP) g_colB[(size_t)d.y * BCAP + p1] = s.y;
    }
}

// pack float4 -> 4 halves (uint2)
__device__ __forceinline__ uint2 pack_h4(float a, float b, float c, float d) {
    __half2 lo = __floats2half2_rn(a, b);
    __half2 hi = __floats2half2_rn(c, d);
    uint2 r;
    r.x = *(unsigned*)&lo;
    r.y = *(unsigned*)&hi;
    return r;
}

// ---------------- fused encoders + GCN0 linear (UNSCALED) : u0 = fp16(relu-concat @ W0) ----------------
#define XS_STRIDE 200   // halves per row (192 + 8 pad)
__global__ void __launch_bounds__(512, 3) k_enc0(
    const float* __restrict__ xf, const float* __restrict__ xw, const float* __restrict__ xt,
    const float* __restrict__ wf, const float* __restrict__ bfir,
    const float* __restrict__ ww, const float* __restrict__ bwea,
    const float* __restrict__ wt, const float* __restrict__ bter,
    const float* __restrict__ W0)
{
    extern __shared__ __align__(16) float sm[];
    float*  Csh   = sm;                     // 64*68 f (stage B)
    float*  Wcomb = sm;                     // 12*192 = 2304 f
    float*  Benc  = Wcomb + 2304;           // 192 f
    float*  raw   = Benc + 192;             // 64*33 = 2112 f
    __half* Wsh   = (__half*)(sm + 4608);   // 12288 h
    __half* xsh   = Wsh + 12288;            // 64*200 h
    const int t = threadIdx.x;

    for (int i = t; i < 12288; i += 512) Wsh[i] = __float2half(W0[i]);
    for (int i = t; i < 2304; i += 512) {
        int k = i / 192, c = i - k * 192;
        float v = 0.f;
        if (c < 64)       { if (k < 8)  v = wf[k * 64 + c]; }
        else if (c < 128) { if (k < 12) v = ww[k * 64 + (c - 64)]; }
        else              { if (k < 10) v = wt[k * 64 + (c - 128)]; }
        Wcomb[i] = v;
    }
    if (t < 64) { Benc[t] = bfir[t]; Benc[64 + t] = bwea[t]; Benc[128 + t] = bter[t]; }

    const int n0g = blockIdx.x * 64;
    for (int i = t; i < 512; i += 512) { int n = i >> 3, k = i & 7;  int gn = n0g + n; raw[n * 33 + k]      = (gn < NN) ? xf[gn * 8 + k]  : 0.f; }
    for (int i = t; i < 768; i += 512) { int n = i / 12, k = i % 12; int gn = n0g + n; raw[n * 33 + 8 + k]  = (gn < NN) ? xw[gn * 12 + k] : 0.f; }
    for (int i = t; i < 640; i += 512) { int n = i / 10, k = i % 10; int gn = n0g + n; raw[n * 33 + 20 + k] = (gn < NN) ? xt[gn * 10 + k] : 0.f; }
    if (t < 64) { raw[t * 33 + 30] = 0.f; raw[t * 33 + 31] = 0.f; }
    __syncthreads();

    // stage A: warp-uniform columns; progressive stores
    {
        const int n = t & 63, g = t >> 6;
        const float* rawn = raw + n * 33;
        uint4* dst = (uint4*)&xsh[n * XS_STRIDE + g * 24];
#pragma unroll
        for (int jg = 0; jg < 3; jg++) {
            unsigned obuf[4];
#pragma unroll
            for (int jp = 0; jp < 4; jp++) {
                float v2[2];
#pragma unroll
                for (int h = 0; h < 2; h++) {
                    const int c = g * 24 + jg * 8 + jp * 2 + h;
                    const int koff = (c < 64) ? 0 : ((c < 128) ? 8 : 20);
                    float v = Benc[c];
#pragma unroll
                    for (int k = 0; k < 12; k++)
                        v = fmaf(rawn[koff + k], Wcomb[k * 192 + c], v);
                    v2[h] = fmaxf(v, 0.f);
                }
                __half2 hh = __floats2half2_rn(v2[0], v2[1]);
                obuf[jp] = *(unsigned*)&hh;
            }
            dst[jg] = make_uint4(obuf[0], obuf[1], obuf[2], obuf[3]);
        }
    }
    __syncthreads();

    // stage B: tensor cores
    {
        const int wid = t >> 5;
        const int wm = wid >> 2, wn = wid & 3;
        wmma::fragment<wmma::matrix_a, 16, 16, 16, __half, wmma::row_major> a;
        wmma::fragment<wmma::matrix_b, 16, 16, 16, __half, wmma::row_major> b;
        wmma::fragment<wmma::accumulator, 16, 16, 16, float> c;
        wmma::fill_fragment(c, 0.0f);
#pragma unroll
        for (int kt = 0; kt < 12; kt++) {
            wmma::load_matrix_sync(a, xsh + wm * 16 * XS_STRIDE + kt * 16, XS_STRIDE);
            wmma::load_matrix_sync(b, Wsh + kt * 16 * 64 + wn * 16, 64);
            wmma::mma_sync(c, a, b, c);
        }
        wmma::store_matrix_sync(Csh + wm * 16 * 68 + wn * 16, c, 68, wmma::mem_row_major);
    }
    __syncthreads();

    // epilogue: pack fp16 UNSCALED (dinv applied by k_scale)
    {
        const int n = t >> 3, cb = (t & 7) * 8;
        const int gn = n0g + n;
        if (gn < NN) {
            const float* cr = Csh + n * 68 + cb;
            uint2 lo = pack_h4(cr[0], cr[1], cr[2], cr[3]);
            uint2 hi = pack_h4(cr[4], cr[5], cr[6], cr[7]);
            uint4 o = make_uint4(lo.x, lo.y, hi.x, hi.y);
            *(uint4*)&g_hs[(size_t)gn * 64 + cb] = o;
        }
    }
}

// ---------------- scale hs by dinv (joins enc0 and fillB) ----------------
__global__ void __launch_bounds__(256) k_scale() {
    int idx = blockIdx.x * 256 + threadIdx.x;    // uint4 index; NN*8 total
    if (idx < NN * 8) {
        int node = idx >> 3;
        float di = rsqrtf((float)g_cnt[node] + 1.0f);
        uint4 v = *(uint4*)&g_hs[(size_t)idx * 8];
        float2 a = __half22float2(*(__half2*)&v.x);
        float2 b = __half22float2(*(__half2*)&v.y);
        float2 c = __half22float2(*(__half2*)&v.z);
        float2 d = __half22float2(*(__half2*)&v.w);
        uint2 lo = pack_h4(di * a.x, di * a.y, di * b.x, di * b.y);
        uint2 hi = pack_h4(di * c.x, di * c.y, di * d.x, di * d.y);
        *(uint4*)&g_hs[(size_t)idx * 8] = make_uint4(lo.x, lo.y, hi.x, hi.y);
    }
}

// ---------------- GCN linear : hs = fp16(dinv .* (x @ W)) , packed f32x2 FMA ----------------
__global__ void __launch_bounds__(256) k_lin(const float* __restrict__ W)
{
    __shared__ __align__(16) float Ws[4096];
    __shared__ __align__(16) float xs[128 * 68];
    const int t = threadIdx.x;
    for (int i = t; i < 4096; i += 256) Ws[i] = W[i];

    const int n0g = blockIdx.x * 128;
    for (int i = t; i < 2048; i += 256) {
        int n = i >> 4, k4 = i & 15;
        int gn = n0g + n;
        float4 v = (gn < NN) ? *(const float4*)&g_x[(size_t)gn * 64 + k4 * 4] : make_float4(0, 0, 0, 0);
        *(float4*)&xs[n * 68 + k4 * 4] = v;
    }
    __syncthreads();

    const int cg = t & 15, rg = t >> 4;
    const int n0 = rg * 8, c0 = cg * 4;
    unsigned long long acc01[8], acc23[8];
#pragma unroll
    for (int i = 0; i < 8; i++) { acc01[i] = 0; acc23[i] = 0; }

#pragma unroll 4
    for (int k = 0; k < 64; k++) {
        float4 b = *(const float4*)&Ws[k * 64 + c0];
        unsigned long long b01, b23;
        PK2(b01, b.x, b.y);
        PK2(b23, b.z, b.w);
#pragma unroll
        for (int i = 0; i < 8; i++) {
            float a = xs[(n0 + i) * 68 + k];
            unsigned long long aa;
            PK2(aa, a, a);
            FMA2(acc01[i], aa, b01);
            FMA2(acc23[i], aa, b23);
        }
    }
#pragma unroll
    for (int i = 0; i < 8; i++) {
        int gn = n0g + n0 + i;
        if (gn < NN) {
            float di = rsqrtf((float)g_cnt[gn] + 1.0f);
            float a0, a1, a2, a3;
            UPK2(a0, a1, acc01[i]);
            UPK2(a2, a3, acc23[i]);
            uint2 o = pack_h4(di * a0, di * a1, di * a2, di * a3);
            *(uint2*)&g_hs[(size_t)gn * 64 + c0] = o;
        }
    }
}

// ---------------- gather aggregation : x = relu(dinv_i * (sum_j hs_j + hs_i) + b) ----------------
// 4 nodes per warp (8 lanes each); 8-edge batches; pairwise fp16 pre-reduction
// (one __hadd2 of two fresh rows, then fp32 accumulate) to cut cvt+FADD count.
__global__ void __launch_bounds__(256, 4) k_gather(const float* __restrict__ bias)
{
    const int lane = threadIdx.x & 31;
    const int warp = threadIdx.x >> 5;
    const int q  = lane >> 3;
    const int ql = lane & 7;
    const int node = blockIdx.x * 32 + warp * 4 + q;

    const int deg = g_cnt[node];
    const int* colb = g_colB + (size_t)node * BCAP;
    const float di = rsqrtf((float)deg + 1.0f);

    uint4 self = *(const uint4*)&g_hs[(size_t)node * 64 + ql * 8];
    float2 a0 = __half22float2(*(__half2*)&self.x);
    float2 a1 = __half22float2(*(__half2*)&self.y);
    float2 a2 = __half22float2(*(__half2*)&self.z);
    float2 a3 = __half22float2(*(__half2*)&self.w);

    int p = 0;
    while (true) {
        int rem = deg - p;
        int mx = rem;
        mx = max(mx, __shfl_xor_sync(0xffffffffu, mx, 8));
        mx = max(mx, __shfl_xor_sync(0xffffffffu, mx, 16));
        if (mx <= 0) break;
        int cnt = min(8, max(rem, 0));
        int idx = (ql < cnt) ? colb[p + ql] : 0;

        uint4 v[8];
#pragma unroll
        for (int r = 0; r < 8; r++) {
            int j = __shfl_sync(0xffffffffu, idx, (q << 3) + r);
            v[r] = (r < cnt) ? *(const uint4*)&g_hs[(size_t)j * 64 + ql * 8]
                             : make_uint4(0u, 0u, 0u, 0u);
        }
        // pairwise fp16 pre-reduction, then fp32 accumulate
#pragma unroll
        for (int r = 0; r < 8; r += 2) {
            __half2 hx = __hadd2(*(__half2*)&v[r].x, *(__half2*)&v[r + 1].x);
            __half2 hy = __hadd2(*(__half2*)&v[r].y, *(__half2*)&v[r + 1].y);
            __half2 hz = __hadd2(*(__half2*)&v[r].z, *(__half2*)&v[r + 1].z);
            __half2 hw = __hadd2(*(__half2*)&v[r].w, *(__half2*)&v[r + 1].w);
            float2 f0 = __half22float2(hx);
            float2 f1 = __half22float2(hy);
            float2 f2 = __half22float2(hz);
            float2 f3 = __half22float2(hw);
            a0.x += f0.x; a0.y += f0.y;
            a1.x += f1.x; a1.y += f1.y;
            a2.x += f2.x; a2.y += f2.y;
            a3.x += f3.x; a3.y += f3.y;
        }
        p += 8;
    }

    float4 bA = *(const float4*)&bias[ql * 8];
    float4 bB = *(const float4*)&bias[ql * 8 + 4];
    float4 oA, oB;
    oA.x = fmaxf(fmaf(di, a0.x, bA.x), 0.f);
    oA.y = fmaxf(fmaf(di, a0.y, bA.y), 0.f);
    oA.z = fmaxf(fmaf(di, a1.x, bA.z), 0.f);
    oA.w = fmaxf(fmaf(di, a1.y, bA.w), 0.f);
    oB.x = fmaxf(fmaf(di, a2.x, bB.x), 0.f);
    oB.y = fmaxf(fmaf(di, a2.y, bB.y), 0.f);
    oB.z = fmaxf(fmaf(di, a3.x, bB.z), 0.f);
    oB.w = fmaxf(fmaf(di, a3.y, bB.w), 0.f);
    *(float4*)&g_x[(size_t)node * 64 + ql * 8]     = oA;
    *(float4*)&g_x[(size_t)node * 64 + ql * 8 + 4] = oB;
}

// ---------------- output MLP : out = relu(x @ W1 + b1) @ W2 + b2 (128 nodes/block) ----------------
__global__ void __launch_bounds__(256) k_out(
    const float* __restrict__ W1, const float* __restrict__ B1,
    const float* __restrict__ W2, const float* __restrict__ B2,
    float* __restrict__ out)
{
    __shared__ float W1s[2048];
    __shared__ float W2s[32];
    __shared__ float B1s[32];
    __shared__ float xsh[8][64];
    const int t = threadIdx.x;
    for (int i = t; i < 2048; i += 256) W1s[i] = W1[i];
    if (t < 32) { W2s[t] = W2[t]; B1s[t] = B1[t]; }
    __syncthreads();

    const int lane = t & 31, w = t >> 5;
#pragma unroll 1
    for (int it = 0; it < 16; it++) {
        const int node = blockIdx.x * 128 + it * 8 + w;
        if (node < NN) {
            xsh[w][lane]      = g_x[(size_t)node * 64 + lane];
            xsh[w][32 + lane] = g_x[(size_t)node * 64 + 32 + lane];
            __syncwarp();
            float m = B1s[lane];
#pragma unroll
            for (int k = 0; k < 64; k++) m = fmaf(xsh[w][k], W1s[k * 32 + lane], m);
            m = fmaxf(m, 0.f) * W2s[lane];
#pragma unroll
            for (int off = 16; off; off >>= 1) m += __shfl_xor_sync(0xffffffffu, m, off);
            if (lane == 0) out[node] = m + B2[0];
            __syncwarp();
        }
    }
}

// ---------------- launch ----------------
extern "C" void kernel_launch(void* const* d_in, const int* in_sizes, int n_in,
                              void* d_out, int out_size)
{
    const float* xf  = (const float*)d_in[0];
    const float* xw  = (const float*)d_in[1];
    const float* xt  = (const float*)d_in[2];
    const void*  ei  = d_in[3];
    const float* wf  = (const float*)d_in[4];
    const float* bf  = (const float*)d_in[5];
    const float* ww  = (const float*)d_in[6];
    const float* bw  = (const float*)d_in[7];
    const float* wt  = (const float*)d_in[8];
    const float* bt  = (const float*)d_in[9];
    const float* w0  = (const float*)d_in[10];
    const float* b0  = (const float*)d_in[11];
    const float* w1  = (const float*)d_in[12];
    const float* b1  = (const float*)d_in[13];
    const float* w2  = (const float*)d_in[14];
    const float* b2  = (const float*)d_in[15];
    const float* ow1 = (const float*)d_in[16];
    const float* ob1 = (const float*)d_in[17];
    const float* ow2 = (const float*)d_in[18];
    const float* ob2 = (const float*)d_in[19];
    float* out = (float*)d_out;

    // one-time host-side objects (no device memory involved)
    static cudaStream_t sB = nullptr;
    static cudaEvent_t  eFork = nullptr, eEnc = nullptr;
    if (sB == nullptr) {
        cudaStreamCreateWithFlags(&sB, cudaStreamNonBlocking);
        cudaEventCreateWithFlags(&eFork, cudaEventDisableTiming);
        cudaEventCreateWithFlags(&eEnc,  cudaEventDisableTiming);
    }

    const int ENC_SMEM = 4608 * 4 + 12288 * 2 + 64 * XS_STRIDE * 2;  // 68608 B
    cudaFuncSetAttribute(k_enc0, cudaFuncAttributeMaxDynamicSharedMemorySize, ENC_SMEM);

    const int encTiles = (NN + 63) / 64;     // 1563
    const int linTiles = (NN + 127) / 128;   // 782
    const int gBlocks  = NN / 32;            // 3125
    const int oBlocks  = (NN + 127) / 128;   // 782
    const int sBlocks  = (NN * 8 + 255) / 256;
    const int ePairs   = EE / 2;

    // fork: enc0 (unscaled, edge-independent) on sB; adjacency build on main stream
    cudaEventRecord(eFork, 0);
    cudaStreamWaitEvent(sB, eFork, 0);
    k_enc0<<<encTiles, 512, ENC_SMEM, sB>>>(xf, xw, xt, wf, bf, ww, bw, wt, bt, w0);
    cudaEventRecord(eEnc, sB);

    k_prep<<<(NN + 255) / 256, 256>>>((const int*)ei);
    k_fillB<<<(ePairs + 255) / 256, 256>>>(ei);

    // join, then scale hs0 by dinv
    cudaStreamWaitEvent(0, eEnc, 0);
    k_scale<<<sBlocks, 256>>>();

    // layer 0 gather
    k_gather<<<gBlocks, 256>>>(b0);
    // layer 1
    k_lin<<<linTiles, 256>>>(w1);
    k_gather<<<gBlocks, 256>>>(b1);
    // layer 2
    k_lin<<<linTiles, 256>>>(w2);
    k_gather<<<gBlocks, 256>>>(b2);
    // output MLP
    k_out<<<oBlocks, 256>>>(ow1, ob1, ow2, ob2, out);
}